// round 11
// baseline (speedup 1.0000x reference)
#include <cuda_runtime.h>
#include <cstdint>

static constexpr int D     = 128;
static constexpr int K     = 8;
static constexpr int WARPS = 8;       // 256 threads/block

__global__ void spl_zero_kernel(float* out) { *out = 0.0f; }

// One pipeline stage: rows + polarity gathers + dims for one 2-pair unit.
struct Stage {
    float4 A0, B0, A1, B1;   // pair0 rows, pair1 rows (this lane's 4 elems)
    float  g1, g2;           // polarity gather values (lanes 0..15)
    int    dim;              // this lane's selected dim (lanes 0..15)
};

__global__ __launch_bounds__(256, 4) void spl_loss_kernel(
    const float* __restrict__ emb,
    const int*   __restrict__ pair_ids,
    const int*   __restrict__ dims,
    float*       __restrict__ out,
    int n_pairs, float inv_p)
{
    const unsigned FULL = 0xFFFFFFFFu;
    const int lane = threadIdx.x & 31;
    const int wid  = threadIdx.x >> 5;
    const int U    = (n_pairs + 1) >> 1;            // 2-pair units
    const int W    = gridDim.x * WARPS;             // warp-slots (grid stride)
    const int wg   = blockIdx.x * WARPS + wid;

    __shared__ float warp_sums[WARPS];

    const long dim_max = (long)n_pairs * K - 1;

    // prefetch ids+dims for unit u (clamped; validity handled at compute)
    auto pre_ids = [&](int u) -> int4 {
        int uu = (u < U) ? u : (U - 1);
        return __ldg((const int4*)pair_ids + uu);
    };
    auto pre_dim = [&](int u) -> int {
        int uu = (u < U) ? u : (U - 1);
        long di = (long)uu * 2 * K + lane;          // lanes 0..15 used
        if (di > dim_max) di = dim_max;
        return __ldg(dims + di);
    };
    // issue all loads for one unit (rows + gathers); no serial chain inside
    auto issue = [&](Stage& s, const int4 ids, const int dm) {
        const float* r0a = emb + (size_t)ids.x * D;
        const float* r0b = emb + (size_t)ids.y * D;
        const float* r1a = emb + (size_t)ids.z * D;
        const float* r1b = emb + (size_t)ids.w * D;
        s.A0 = __ldg((const float4*)r0a + lane);
        s.B0 = __ldg((const float4*)r0b + lane);
        s.A1 = __ldg((const float4*)r1a + lane);
        s.B1 = __ldg((const float4*)r1b + lane);
        s.dim = dm;
        s.g1 = 0.0f; s.g2 = 0.0f;
        if (lane < 16) {
            const float* ra = (lane & 8) ? r1a : r0a;
            const float* rb = (lane & 8) ? r1b : r0b;
            s.g1 = __ldg(ra + dm);
            s.g2 = __ldg(rb + dm);
        }
    };
    float c = 0.0f;
    auto compute = [&](const Stage& s, int u) {
        const bool v0 = (2 * u)     < n_pairs;
        const bool v1 = (2 * u + 1) < n_pairs;
        const bool pol = (lane < 8) ? v0 : (lane < 16 && v1);

        // duplicate-dim detection: MATCH + ballot (distinct dims -> leader lanes)
        int key = pol ? (s.dim + ((lane & 8) << 5)) : (0x8000 + lane);
        unsigned mm = __match_any_sync(FULL, key);
        bool leader = ((mm & ((1u << lane) - 1u)) == 0u);
        unsigned lb = __ballot_sync(FULL, leader && pol);
        int d0 = __popc(lb & 0x00FFu);
        int d1 = __popc(lb & 0xFF00u);
        float invk0 = v0 ? __fdividef(0.5f, (float)(D - d0)) : 0.0f;
        float invk1 = v1 ? __fdividef(0.5f, (float)(D - d1)) : 0.0f;

        float dx, dy, dz, dw;
        dx = s.A0.x - s.B0.x; dy = s.A0.y - s.B0.y;
        dz = s.A0.z - s.B0.z; dw = s.A0.w - s.B0.w;
        float t0 = fmaf(dx, dx, fmaf(dy, dy, fmaf(dz, dz, dw * dw)));
        dx = s.A1.x - s.B1.x; dy = s.A1.y - s.B1.y;
        dz = s.A1.z - s.B1.z; dw = s.A1.w - s.B1.w;
        float t1 = fmaf(dx, dx, fmaf(dy, dy, fmaf(dz, dz, dw * dw)));
        c = fmaf(t0, invk0, fmaf(t1, invk1, c));

        if (pol) {
            // polarity (duplicates counted; sign_prod==0 iff either value is +-0)
            float sm  = fabsf(s.g1) + fabsf(s.g2);
            bool zero = (s.g1 == 0.0f) || (s.g2 == 0.0f);
            bool opp  = ((__float_as_int(s.g1) ^ __float_as_int(s.g2)) < 0);
            c += zero ? 0.1f : (opp ? -0.5f * sm : sm);
            if (leader) {       // subtract selected-dim diff^2 (distinct only)
                float dd = s.g1 - s.g2;
                c = fmaf(-dd * dd, (lane & 8) ? invk1 : invk0, c);
            }
        }
    };

    int u = wg;
    if (u < U) {
        // ---- pipeline prologue ----
        int4 idA = pre_ids(u);
        int  dmA = pre_dim(u);
        Stage s0, s1;
        issue(s0, idA, dmA);
        int4 idB = pre_ids(u + W);
        int  dmB = pre_dim(u + W);

        // ---- steady state: compute(u) overlaps rows(u+W) and ids(u+2W) ----
        while (true) {
            if (u + W < U) issue(s1, idB, dmB);
            if (u + 2 * W < U) { idA = pre_ids(u + 2 * W); dmA = pre_dim(u + 2 * W); }
            compute(s0, u);
            if (u + W >= U) break;
            u += W;

            if (u + W < U) issue(s0, idA, dmA);
            if (u + 2 * W < U) { idB = pre_ids(u + 2 * W); dmB = pre_dim(u + 2 * W); }
            compute(s1, u);
            if (u + W >= U) break;
            u += W;
        }
    }

    // ---- warp butterfly + block reduce + one atomic per block ----
    #pragma unroll
    for (int off = 16; off > 0; off >>= 1)
        c += __shfl_xor_sync(FULL, c, off);
    if (lane == 0) warp_sums[wid] = c;
    __syncthreads();
    if (threadIdx.x == 0) {
        float s = 0.0f;
        #pragma unroll
        for (int v = 0; v < WARPS; v++) s += warp_sums[v];
        atomicAdd(out, s * inv_p);
    }
}

extern "C" void kernel_launch(void* const* d_in, const int* in_sizes, int n_in,
                              void* d_out, int out_size)
{
    const float* emb      = (const float*)d_in[0];  // (VOCAB, 128) f32
    const int*   pair_ids = (const int*)  d_in[1];  // (P, 2) i32
    const int*   dims     = (const int*)  d_in[2];  // (P, 8) i32
    float*       out      = (float*)d_out;          // scalar f32

    int n_pairs = in_sizes[1] / 2;
    spl_zero_kernel<<<1, 1>>>(out);

    // Persistent-style grid: ~4 blocks/SM x 148 SMs; each warp pipelines
    // ~10 two-pair units, keeping loads continuously in flight.
    int U = (n_pairs + 1) / 2;
    int blocks = 592;
    int max_blocks = (U + WARPS - 1) / WARPS;
    if (blocks > max_blocks) blocks = max_blocks;
    spl_loss_kernel<<<blocks, 256>>>(emb, pair_ids, dims, out,
                                     n_pairs, 1.0f / (float)n_pairs);
}